// round 16
// baseline (speedup 1.0000x reference)
#include <cuda_runtime.h>
#include <cuda_bf16.h>
#include <math.h>

#define TOT 21330
#define COLS_T 10700
#define CPAD 10752
typedef unsigned long long ull;

__constant__ int   c_H[5]    = {100, 50, 25, 13, 7};
__constant__ int   c_W[5]    = {160, 80, 40, 20, 10};
__constant__ int   c_off[5]  = {0, 16000, 20000, 21000, 21260};
__constant__ float c_str[5]  = {8.f, 16.f, 32.f, 64.f, 128.f};
__constant__ int   c_HW[5]   = {16000, 4000, 1000, 260, 70};
__constant__ int   c_lt2[4]  = {4000, 5000, 5260, 5330};
__constant__ int   c_lo2[5]  = {0, 4000, 5000, 5260, 5330};
__constant__ int   c_len2[5] = {4000, 1000, 260, 70, 20};
__constant__ int   c_tw2[5]  = {80, 40, 20, 10, 5};

static const int OFFS[5] = {0, 16000, 20000, 21000, 21260};

#define LVL_ELEMS (512 * 21330)
__device__ float g_buf[4][LVL_ELEMS];     // raw conv outputs [tower*2+pp]
__device__ float g_affs[10 * 512];
__device__ float g_affb[10 * 512];
__device__ float g_p2[2 * CPAD * 64];     // per-(t,col) GN partials [col][g*2+w]
__device__ float g_p3[20 * 8 * 64];       // stage-1 partials [(t,l,n)][split][64]
__device__ float g_bias[10 * 256];
// winograd buffers (bf16 hi/lo split); slots 0-3 cls, 4-7 box, 8 score, 9 pred+ctr
__device__ __align__(16) __nv_bfloat16 g_Uh[(size_t)10 * 16 * 256 * 256];   // [slot][xn][oc][k]
__device__ __align__(16) __nv_bfloat16 g_Ul[(size_t)10 * 16 * 256 * 256];
__device__ __align__(16) __nv_bfloat16 g_Vh[(size_t)2 * 16 * CPAD * 256];   // [t][xn][col][k]
__device__ __align__(16) __nv_bfloat16 g_Vl[(size_t)2 * 16 * CPAD * 256];
__device__ float g_M[(size_t)2 * 16 * CPAD * 256];                          // [t][xn][col][oc]

struct P5  { const float* p[5]; };
struct P5o { float* p[5]; };

__device__ __forceinline__ float sigmoidf_(float v) { return 1.f / (1.f + expf(-v)); }

#define CP16(dst, src) \
    asm volatile("cp.async.cg.shared.global [%0], [%1], 16;" :: "r"(dst), "l"(src))
#define CP_COMMIT() asm volatile("cp.async.commit_group;" ::: "memory")
#define CP_WAIT2()  asm volatile("cp.async.wait_group 2;" ::: "memory")
#define CP_WAIT1()  asm volatile("cp.async.wait_group 1;" ::: "memory")
#define CP_WAIT0()  asm volatile("cp.async.wait_group 0;" ::: "memory")

#define LDSM4(r0, r1, r2, r3, a) \
    asm volatile("ldmatrix.sync.aligned.m8n8.x4.shared.b16 {%0,%1,%2,%3}, [%4];" \
        : "=r"(r0), "=r"(r1), "=r"(r2), "=r"(r3) : "r"(a))
#define MMA16816(c0, c1, c2, c3, a0, a1, a2, a3, b0, b1) \
    asm volatile("mma.sync.aligned.m16n8k16.row.col.f32.bf16.bf16.f32 " \
        "{%0,%1,%2,%3}, {%4,%5,%6,%7}, {%8,%9}, {%0,%1,%2,%3};" \
        : "+f"(c0), "+f"(c1), "+f"(c2), "+f"(c3) \
        : "r"(a0), "r"(a1), "r"(a2), "r"(a3), "r"(b0), "r"(b1))

// ============ bias pack (one-time) ============
__global__ __launch_bounds__(256) void bias_k(
    const float* __restrict__ cb, const float* __restrict__ bb,
    const float* __restrict__ sb, const float* __restrict__ pb,
    const float* __restrict__ tb)
{
    int slot = blockIdx.x;
    int c = threadIdx.x;
    float b = 0.f;
    if (slot < 4)       b = cb[slot * 256 + c];
    else if (slot < 8)  b = bb[(slot - 4) * 256 + c];
    else if (slot == 8) { if (c < 80) b = sb[c]; }
    else                { if (c < 4) b = pb[c]; else if (c == 4) b = tb[0]; }
    g_bias[slot * 256 + c] = b;
}

// winograd weight transform -> bf16 hi/lo. grid (256, 10)
__global__ __launch_bounds__(256) void uwt_k(
    const float* __restrict__ cw, const float* __restrict__ bw,
    const float* __restrict__ sw, const float* __restrict__ pw,
    const float* __restrict__ tw)
{
    int slot = blockIdx.y;
    int idx = blockIdx.x * 256 + threadIdx.x;
    int ic = idx & 255, oc = idx >> 8;
    float gg[9];
    const float* g = nullptr;
    if (slot < 4)       g = cw + ((size_t)(slot * 256 + oc) * 256 + ic) * 9;
    else if (slot < 8)  g = bw + ((size_t)((slot - 4) * 256 + oc) * 256 + ic) * 9;
    else if (slot == 8) { if (oc < 80) g = sw + ((size_t)oc * 256 + ic) * 9; }
    else                { if (oc < 4) g = pw + ((size_t)oc * 256 + ic) * 9;
                          else if (oc == 4) g = tw + (size_t)ic * 9; }
#pragma unroll
    for (int j = 0; j < 9; j++) gg[j] = g ? g[j] : 0.f;

    float G0[3], T1[3], T2[3], G2[3];
#pragma unroll
    for (int j = 0; j < 3; j++) {
        float a = gg[j], b = gg[3 + j], c = gg[6 + j];
        G0[j] = a;
        T1[j] = 0.5f * (a + b + c);
        T2[j] = 0.5f * (a - b + c);
        G2[j] = c;
    }
    float u[16];
    const float* rows[4] = {G0, T1, T2, G2};
#pragma unroll
    for (int i = 0; i < 4; i++) {
        const float* t = rows[i];
        u[i * 4 + 0] = t[0];
        u[i * 4 + 1] = 0.5f * (t[0] + t[1] + t[2]);
        u[i * 4 + 2] = 0.5f * (t[0] - t[1] + t[2]);
        u[i * 4 + 3] = t[2];
    }
#pragma unroll
    for (int x = 0; x < 16; x++) {
        float f = u[x];
        __nv_bfloat16 h = __float2bfloat16(f);
        __nv_bfloat16 lo = __float2bfloat16(f - __bfloat162float(h));
        size_t off = (((size_t)(slot * 16 + x) * 256 + oc) * 256 + ic);
        g_Uh[off] = h;
        g_Ul[off] = lo;
    }
}

// ============ input transform (merged towers) -> V[t], bf16 hi/lo ============
// grid (335, nt*32): t = y>>5, icb = (y&31)*8
__global__ __launch_bounds__(256) void itr_k(P5 x0, P5 x1, int useaff)
{
    __shared__ float s[16][8][33];
    const int tid = threadIdx.x;
    const int lane = tid & 31, wid = tid >> 5;
    const int col = blockIdx.x * 32 + lane;
    const int t = blockIdx.y >> 5;
    const int icb = (blockIdx.y & 31) * 8;
    const int ic = icb + wid;

    float v[16];
    {
        bool oob = (col >= COLS_T);
        int lc = oob ? 0 : col;
        int n = 0;
        if (lc >= 5350) { n = 1; lc -= 5350; }
        int l = 0;
#pragma unroll
        for (int q = 0; q < 4; q++) if (lc >= c_lt2[q]) l = q + 1;
        int tile = lc - c_lo2[l];
        int tw2 = c_tw2[l];
        int ty = tile / tw2, tx = tile - ty * tw2;
        int H = c_H[l], W = c_W[l];
        const float* x = (t ? x1.p[l] : x0.p[l]) + ((size_t)n * 256 + ic) * H * W;
        float sa = 1.f, sb = 0.f;
        if (useaff) {
            int as = (t * 5 + l) * 512 + n * 256 + ic;
            sa = g_affs[as]; sb = g_affb[as];
        }
        int h0 = 2 * ty - 1, w0 = 2 * tx - 1;
        float d[4][4];
#pragma unroll
        for (int r = 0; r < 4; r++) {
            int h = h0 + r;
#pragma unroll
            for (int c = 0; c < 4; c++) {
                int w = w0 + c;
                float vv = 0.f;
                if (!oob && h >= 0 && h < H && w >= 0 && w < W) {
                    vv = x[h * W + w];
                    if (useaff) vv = fmaxf(fmaf(vv, sa, sb), 0.f);
                }
                d[r][c] = vv;
            }
        }
        float z[4][4];
#pragma unroll
        for (int j = 0; j < 4; j++) {
            z[0][j] = d[0][j] - d[2][j];
            z[1][j] = d[1][j] + d[2][j];
            z[2][j] = d[2][j] - d[1][j];
            z[3][j] = d[1][j] - d[3][j];
        }
#pragma unroll
        for (int i = 0; i < 4; i++) {
            v[i * 4 + 0] = z[i][0] - z[i][2];
            v[i * 4 + 1] = z[i][1] + z[i][2];
            v[i * 4 + 2] = z[i][2] - z[i][1];
            v[i * 4 + 3] = z[i][1] - z[i][3];
        }
    }
#pragma unroll
    for (int x = 0; x < 16; x++) s[x][wid][lane] = v[x];
    __syncthreads();

#pragma unroll
    for (int r = 0; r < 2; r++) {
        int p = tid + 256 * r;
        int xn = p >> 5, c = p & 31;
        int col2 = blockIdx.x * 32 + c;
        union { __nv_bfloat16 b[8]; uint4 q; } hh, ll;
#pragma unroll
        for (int i = 0; i < 8; i++) {
            float f = s[xn][i][c];
            __nv_bfloat16 h = __float2bfloat16(f);
            hh.b[i] = h;
            ll.b[i] = __float2bfloat16(f - __bfloat162float(h));
        }
        size_t off = (((size_t)(t * 16 + xn) * CPAD + col2) * 256 + icb);
        *(uint4*)(g_Vh + off) = hh.q;
        *(uint4*)(g_Vl + off) = ll.q;
    }
}

// ============ HMMA GEMM (merged towers): M[t][xn][col][oc] ============
#define MG_SMEM (3 * 32768)

__global__ __launch_bounds__(256, 2) void mmag_k(int slot0, int slot1, int v0, int v1)
{
    extern __shared__ char mgsm[];

    const int tid = threadIdx.x, lane = tid & 31, wid = tid >> 5;
    const int cb = blockIdx.x, ob = blockIdx.y;
    const int t = blockIdx.z >> 4, xn = blockIdx.z & 15;
    const int slot = t ? slot1 : slot0;
    const int vt = t ? v1 : v0;
    const int wm = (wid & 3) * 32, wn = (wid >> 2) * 64;
    const unsigned sbu = (unsigned)__cvta_generic_to_shared(mgsm);

    const size_t aRow = ((size_t)(vt * 16 + xn) * CPAD + (size_t)cb * 128);
    const size_t bRow = ((size_t)(slot * 16 + xn) * 256 + ob * 128);

    float acc[2][8][4];
#pragma unroll
    for (int mt = 0; mt < 2; mt++)
#pragma unroll
        for (int nt = 0; nt < 8; nt++)
#pragma unroll
            for (int e = 0; e < 4; e++) acc[mt][nt][e] = 0.f;

    auto stage = [&](int buf, int it) {
        const int tt = it >> 2, kk = (it & 3) << 6;
        const __nv_bfloat16* A = (tt < 2) ? g_Vh : g_Vl;
        const __nv_bfloat16* B = (tt == 1) ? g_Ul : g_Uh;
#pragma unroll
        for (int j = 0; j < 4; j++) {
            int idx = tid + j * 256;
            int r = idx >> 3, c = idx & 7;
            unsigned d = sbu + buf * 32768 + r * 128 + ((c ^ (r & 7)) << 4);
            CP16(d, (const char*)(A + (aRow + r) * 256 + kk) + c * 16);
        }
#pragma unroll
        for (int j = 0; j < 4; j++) {
            int idx = tid + j * 256;
            int r = idx >> 3, c = idx & 7;
            unsigned d = sbu + buf * 32768 + 16384 + r * 128 + ((c ^ (r & 7)) << 4);
            CP16(d, (const char*)(B + (bRow + r) * 256 + kk) + c * 16);
        }
        CP_COMMIT();
    };

    stage(0, 0);
    stage(1, 1);

    for (int it = 0; it < 12; it++) {
        const int buf = it % 3;
        if (it < 10)      { stage((it + 2) % 3, it + 2); CP_WAIT2(); }
        else if (it == 10) CP_WAIT1();
        else               CP_WAIT0();
        __syncthreads();

        const unsigned sA = sbu + buf * 32768;
        const unsigned sB = sA + 16384;
#pragma unroll
        for (int k16 = 0; k16 < 4; k16++) {
            unsigned a[2][4];
#pragma unroll
            for (int mt = 0; mt < 2; mt++) {
                int row = wm + mt * 16 + (lane & 15);
                int lc = 2 * k16 + (lane >> 4);
                unsigned ad = sA + row * 128 + ((lc ^ (row & 7)) << 4);
                LDSM4(a[mt][0], a[mt][1], a[mt][2], a[mt][3], ad);
            }
#pragma unroll
            for (int np = 0; np < 4; np++) {
                int row = wn + np * 16 + (lane & 7) + ((lane >> 4) << 3);
                int lc = 2 * k16 + ((lane >> 3) & 1);
                unsigned bd = sB + row * 128 + ((lc ^ (row & 7)) << 4);
                unsigned b0, b1, b2, b3;
                LDSM4(b0, b1, b2, b3, bd);
#pragma unroll
                for (int mt = 0; mt < 2; mt++) {
                    MMA16816(acc[mt][2*np][0], acc[mt][2*np][1],
                             acc[mt][2*np][2], acc[mt][2*np][3],
                             a[mt][0], a[mt][1], a[mt][2], a[mt][3], b0, b1);
                    MMA16816(acc[mt][2*np+1][0], acc[mt][2*np+1][1],
                             acc[mt][2*np+1][2], acc[mt][2*np+1][3],
                             a[mt][0], a[mt][1], a[mt][2], a[mt][3], b2, b3);
                }
            }
        }
        __syncthreads();
    }

    const int q = lane >> 2, oc2 = 2 * (lane & 3);
#pragma unroll
    for (int mt = 0; mt < 2; mt++) {
#pragma unroll
        for (int rr = 0; rr < 2; rr++) {
            int col = cb * 128 + wm + mt * 16 + q + rr * 8;
            if (col >= COLS_T) continue;
            float* Mp = g_M + ((size_t)(t * 16 + xn) * CPAD + col) * 256 + ob * 128 + wn + oc2;
#pragma unroll
            for (int nt = 0; nt < 8; nt++)
                *(float2*)(Mp + nt * 8) = make_float2(acc[mt][nt][rr * 2],
                                                      acc[mt][nt][rr * 2 + 1]);
        }
    }
}

__device__ __forceinline__ void coldec(int col, int& n, int& l, int& ty, int& tx)
{
    n = 0; int lc = col;
    if (lc >= 5350) { n = 1; lc -= 5350; }
    l = 0;
#pragma unroll
    for (int q = 0; q < 4; q++) if (lc >= c_lt2[q]) l = q + 1;
    int tile = lc - c_lo2[l];
    int tw2 = c_tw2[l];
    ty = tile / tw2; tx = tile - ty * tw2;
}

__device__ __forceinline__ void otr_core(const float* Mp, float bias,
                                         float& y00, float& y01, float& y10, float& y11)
{
    float m[16];
#pragma unroll
    for (int x = 0; x < 16; x++) m[x] = Mp[(size_t)x * CPAD * 256];
    float s0[4], s1[4];
#pragma unroll
    for (int j = 0; j < 4; j++) {
        s0[j] = m[j] + m[4 + j] + m[8 + j];
        s1[j] = m[4 + j] - m[8 + j] - m[12 + j];
    }
    y00 = s0[0] + s0[1] + s0[2] + bias;
    y01 = s0[1] - s0[2] - s0[3] + bias;
    y10 = s1[0] + s1[1] + s1[2] + bias;
    y11 = s1[1] - s1[2] - s1[3] + bias;
}

// ============ tower output transform + GN partial sums. grid (COLS_T, 2) ============
__global__ __launch_bounds__(256) void otr_k(P5o Y0, P5o Y1, int slot0, int slot1)
{
    __shared__ float s1a[256], s2a[256];
    int oc = threadIdx.x;
    int col = blockIdx.x;
    int t = blockIdx.y;
    int slot = t ? slot1 : slot0;
    int n, l, ty, tx;
    coldec(col, n, l, ty, tx);
    int H = c_H[l], W = c_W[l];

    float y00, y01, y10, y11;
    otr_core(g_M + ((size_t)t * 16 * CPAD + col) * 256 + oc,
             g_bias[slot * 256 + oc], y00, y01, y10, y11);

    float* y = (t ? Y1.p[l] : Y0.p[l]) + ((size_t)n * 256 + oc) * H * W;
    int h0 = 2 * ty, w0 = 2 * tx;
    bool v01 = (w0 + 1 < W), v1x = (h0 + 1 < H);
    y[h0 * W + w0] = y00;
    if (v01) y[h0 * W + w0 + 1] = y01;
    if (v1x) {
        y[(h0 + 1) * W + w0] = y10;
        if (v01) y[(h0 + 1) * W + w0 + 1] = y11;
    }

    float sm = y00, sq = y00 * y00;
    if (v01) { sm += y01; sq += y01 * y01; }
    if (v1x) {
        sm += y10; sq += y10 * y10;
        if (v01) { sm += y11; sq += y11 * y11; }
    }
    s1a[oc] = sm; s2a[oc] = sq;
    __syncthreads();
    if (oc < 32) {
        float a = 0.f, b = 0.f;
#pragma unroll
        for (int k = 0; k < 8; k++) { a += s1a[oc * 8 + k]; b += s2a[oc * 8 + k]; }
        g_p2[((size_t)t * CPAD + col) * 64 + oc * 2 + 0] = a;
        g_p2[((size_t)t * CPAD + col) * 64 + oc * 2 + 1] = b;
    }
}

// ============ GN reduce stage 1: coalesced sweep of g_p2. grid (20, 8) ============
// blockIdx.x -> (t = x/10, l = (x%10)/2, n = x%2). 256 thr = 64 elems x 4 rows.
__global__ __launch_bounds__(256) void gnp2_k()
{
    const int bx = blockIdx.x, j = blockIdx.y;
    const int t = bx / 10, rem = bx % 10, l = rem >> 1, n = rem & 1;
    const int tid = threadIdx.x;
    const int e = tid & 63, rg = tid >> 6;
    const int base = n * 5350 + c_lo2[l];
    const int len = c_len2[l];
    const int chunk = (len + 7) >> 3;
    const int beg = j * chunk, end = min(len, beg + chunk);

    float acc = 0.f;
    for (int r = beg + rg; r < end; r += 4)
        acc += g_p2[((size_t)t * CPAD + base + r) * 64 + e];

    __shared__ float s[4][64];
    s[rg][e] = acc;
    __syncthreads();
    if (tid < 64) {
        float v = s[0][tid] + s[1][tid] + s[2][tid] + s[3][tid];
        g_p3[(bx * 8 + j) * 64 + tid] = v;
    }
}

// ============ GN reduce stage 2 + affine finalize. grid 20, 256 thr ============
__global__ __launch_bounds__(256) void gnfin_k(
    const float* __restrict__ cgw, const float* __restrict__ cgb,
    const float* __restrict__ bgw, const float* __restrict__ bgb, int i)
{
    const int bx = blockIdx.x;
    const int t = bx / 10, rem = bx % 10, l = rem >> 1, n = rem & 1;
    const int tid = threadIdx.x;
    __shared__ float s[64];
    if (tid < 64) {
        float v = 0.f;
#pragma unroll
        for (int j = 0; j < 8; j++) v += g_p3[(bx * 8 + j) * 64 + tid];
        s[tid] = v;
    }
    __syncthreads();
    int c = tid, g = c >> 3;
    float inv = 1.f / (8.f * (float)c_HW[l]);
    float mean = s[g * 2 + 0] * inv;
    float var = s[g * 2 + 1] * inv - mean * mean;
    float rstd = rsqrtf(var + 1e-5f);
    const float* gw = t ? bgw : cgw;
    const float* gb = t ? bgb : cgb;
    float sc = gw[i * 256 + c] * rstd;
    g_affs[(t * 5 + l) * 512 + n * 256 + c] = sc;
    g_affb[(t * 5 + l) * 512 + n * 256 + c] = gb[i * 256 + c] - mean * sc;
}

// ============ merged head output transform. grid COLS_T, 128 thr ============
// threads 96..100: box decode (M[1], slot 9) -> out boxes, sigmoid(ctr) -> smem
// threads 0..79:   score (M[0], slot 8) * sigmoid(ctr) -> out scores
__global__ __launch_bounds__(128) void otrH_k(float* __restrict__ out,
                                              const float* __restrict__ scales)
{
    __shared__ float sc4[4];
    int tid = threadIdx.x;
    int col = blockIdx.x;
    int n, l, ty, tx;
    coldec(col, n, l, ty, tx);
    int H = c_H[l], W = c_W[l];
    int h0 = 2 * ty, w0 = 2 * tx;

    if (tid >= 96 && tid <= 100) {
        int oc = tid - 96;
        float st = c_str[l];
        float sl = scales[l];
        float y4[4];
        otr_core(g_M + ((size_t)16 * CPAD + col) * 256 + oc,
                 g_bias[9 * 256 + oc], y4[0], y4[1], y4[2], y4[3]);
#pragma unroll
        for (int dy = 0; dy < 2; dy++)
#pragma unroll
            for (int dx = 0; dx < 2; dx++) {
                int gh = h0 + dy, gw = w0 + dx;
                if (gh >= H || gw >= W) continue;
                float v = y4[dy * 2 + dx];
                int pix = c_off[l] + gh * W + gw;
                if (oc == 4) {
                    sc4[dy * 2 + dx] = sigmoidf_(v);
                } else {
                    float rg = fmaxf(v * sl, 0.f) * st;
                    float sh = (oc & 1) ? gh * st : gw * st;
                    out[((size_t)n * TOT + pix) * 84 + 80 + oc] = (oc < 2) ? sh - rg : sh + rg;
                }
            }
    }
    __syncthreads();

    if (tid < 80) {
        int oc = tid;
        float y4[4];
        otr_core(g_M + (size_t)col * 256 + oc, g_bias[8 * 256 + oc],
                 y4[0], y4[1], y4[2], y4[3]);
        size_t base = (size_t)n * TOT;
#pragma unroll
        for (int dy = 0; dy < 2; dy++)
#pragma unroll
            for (int dx = 0; dx < 2; dx++) {
                int gh = h0 + dy, gw = w0 + dx;
                if (gh >= H || gw >= W) continue;
                int pix = c_off[l] + gh * W + gw;
                out[(base + pix) * 84 + oc] = sigmoidf_(y4[dy * 2 + dx]) * sc4[dy * 2 + dx];
            }
    }
}

// ============ host ============
extern "C" void kernel_launch(void* const* d_in, const int* in_sizes, int n_in,
                              void* d_out, int out_size)
{
    (void)in_sizes; (void)n_in; (void)out_size;

    const float* feats[5];
    for (int i = 0; i < 5; i++) feats[i] = (const float*)d_in[i];
    const float* cls_w  = (const float*)d_in[5];
    const float* cls_b  = (const float*)d_in[6];
    const float* cls_gw = (const float*)d_in[7];
    const float* cls_gb = (const float*)d_in[8];
    const float* box_w  = (const float*)d_in[9];
    const float* box_b  = (const float*)d_in[10];
    const float* box_gw = (const float*)d_in[11];
    const float* box_gb = (const float*)d_in[12];
    const float* score_w = (const float*)d_in[13];
    const float* score_b = (const float*)d_in[14];
    const float* pred_w  = (const float*)d_in[15];
    const float* pred_b  = (const float*)d_in[16];
    const float* ctr_w   = (const float*)d_in[17];
    const float* ctr_b   = (const float*)d_in[18];
    const float* scales  = (const float*)d_in[19];
    float* out = (float*)d_out;

    float* bufp;
    cudaGetSymbolAddress((void**)&bufp, g_buf);
    auto lvl = [&](int t, int pp, int l) {
        return bufp + (size_t)(t * 2 + pp) * LVL_ELEMS + (size_t)512 * OFFS[l];
    };
    auto mkP5o = [&](int t, int pp) {
        P5o y; for (int l = 0; l < 5; l++) y.p[l] = lvl(t, pp, l); return y;
    };
    auto mkP5 = [&](int t, int pp) {
        P5 y; for (int l = 0; l < 5; l++) y.p[l] = lvl(t, pp, l); return y;
    };

    cudaFuncSetAttribute(mmag_k, cudaFuncAttributeMaxDynamicSharedMemorySize, MG_SMEM);

    dim3 blk(256);

    // one-time weight prep
    bias_k<<<10, blk>>>(cls_b, box_b, score_b, pred_b, ctr_b);
    uwt_k<<<dim3(256, 10), blk>>>(cls_w, box_w, score_w, pred_w, ctr_w);

    // depth 0: single shared V (identical inputs, no affine)
    {
        P5 F; for (int l = 0; l < 5; l++) F.p[l] = feats[l];
        itr_k<<<dim3(335, 32), blk>>>(F, F, 0);
        mmag_k<<<dim3(84, 2, 32), blk, MG_SMEM>>>(0, 4, 0, 0);
        otr_k<<<dim3(COLS_T, 2), blk>>>(mkP5o(0, 0), mkP5o(1, 0), 0, 4);
        gnp2_k<<<dim3(20, 8), blk>>>();
        gnfin_k<<<20, blk>>>(cls_gw, cls_gb, box_gw, box_gb, 0);
    }
    // depths 1..3: merged towers
    for (int i = 1; i < 4; i++) {
        itr_k<<<dim3(335, 64), blk>>>(mkP5(0, (i - 1) & 1), mkP5(1, (i - 1) & 1), 1);
        mmag_k<<<dim3(84, 2, 32), blk, MG_SMEM>>>(i, 4 + i, 0, 1);
        otr_k<<<dim3(COLS_T, 2), blk>>>(mkP5o(0, i & 1), mkP5o(1, i & 1), i, 4 + i);
        gnp2_k<<<dim3(20, 8), blk>>>();
        gnfin_k<<<20, blk>>>(cls_gw, cls_gb, box_gw, box_gb, i);
    }

    // heads (inputs: depth-3 outputs pp=1; affines i=3)
    itr_k<<<dim3(335, 64), blk>>>(mkP5(0, 1), mkP5(1, 1), 1);
    mmag_k<<<dim3(84, 1, 32), blk, MG_SMEM>>>(8, 9, 0, 1);
    otrH_k<<<COLS_T, 128>>>(out, scales);
}

// round 17
// speedup vs baseline: 1.0522x; 1.0522x over previous
#include <cuda_runtime.h>
#include <cuda_bf16.h>
#include <math.h>

#define TOT 21330
#define COLS_T 10700
#define CPAD 10752
typedef unsigned long long ull;

__constant__ int   c_H[5]   = {100, 50, 25, 13, 7};
__constant__ int   c_W[5]   = {160, 80, 40, 20, 10};
__constant__ int   c_off[5] = {0, 16000, 20000, 21000, 21260};
__constant__ float c_str[5] = {8.f, 16.f, 32.f, 64.f, 128.f};
__constant__ int   c_HW[5]  = {16000, 4000, 1000, 260, 70};
__constant__ int   c_lt2[4] = {4000, 5000, 5260, 5330};
__constant__ int   c_lo2[5] = {0, 4000, 5000, 5260, 5330};
__constant__ int   c_tw2[5] = {80, 40, 20, 10, 5};

static const int OFFS[5] = {0, 16000, 20000, 21000, 21260};

#define LVL_ELEMS (512 * 21330)
__device__ float g_buf[4][LVL_ELEMS];     // raw conv outputs [tower*2+pp]
__device__ float g_affs[10 * 512];
__device__ float g_affb[10 * 512];
__device__ float g_part[10 * 64 * 4 * 2];
__device__ float g_bias[10 * 256];
// winograd buffers (bf16 hi/lo split); slots 0-3 cls, 4-7 box, 8 score, 9 pred+ctr
__device__ __align__(16) __nv_bfloat16 g_Uh[(size_t)10 * 16 * 256 * 256];  // [slot][xn][oc][k]
__device__ __align__(16) __nv_bfloat16 g_Ul[(size_t)10 * 16 * 256 * 256];
__device__ __align__(16) __nv_bfloat16 g_Vh[(size_t)16 * CPAD * 256];      // [xn][col][k]
__device__ __align__(16) __nv_bfloat16 g_Vl[(size_t)16 * CPAD * 256];
__device__ float g_M[(size_t)2 * 16 * CPAD * 256];  // [mo][xn][col][oc] fp32

struct P5  { const float* p[5]; };
struct P5o { float* p[5]; };

__device__ __forceinline__ float sigmoidf_(float v) { return 1.f / (1.f + expf(-v)); }

#define CP16(dst, src) \
    asm volatile("cp.async.cg.shared.global [%0], [%1], 16;" :: "r"(dst), "l"(src))
#define CP_COMMIT() asm volatile("cp.async.commit_group;" ::: "memory")
#define CP_WAIT2()  asm volatile("cp.async.wait_group 2;" ::: "memory")
#define CP_WAIT1()  asm volatile("cp.async.wait_group 1;" ::: "memory")
#define CP_WAIT0()  asm volatile("cp.async.wait_group 0;" ::: "memory")

#define LDSM4(r0, r1, r2, r3, a) \
    asm volatile("ldmatrix.sync.aligned.m8n8.x4.shared.b16 {%0,%1,%2,%3}, [%4];" \
        : "=r"(r0), "=r"(r1), "=r"(r2), "=r"(r3) : "r"(a))
#define MMA16816(c0, c1, c2, c3, a0, a1, a2, a3, b0, b1) \
    asm volatile("mma.sync.aligned.m16n8k16.row.col.f32.bf16.bf16.f32 " \
        "{%0,%1,%2,%3}, {%4,%5,%6,%7}, {%8,%9}, {%0,%1,%2,%3};" \
        : "+f"(c0), "+f"(c1), "+f"(c2), "+f"(c3) \
        : "r"(a0), "r"(a1), "r"(a2), "r"(a3), "r"(b0), "r"(b1))

// ============ bias pack (one-time) ============
__global__ __launch_bounds__(256) void bias_k(
    const float* __restrict__ cb, const float* __restrict__ bb,
    const float* __restrict__ sb, const float* __restrict__ pb,
    const float* __restrict__ tb)
{
    int slot = blockIdx.x;
    int c = threadIdx.x;
    float b = 0.f;
    if (slot < 4)       b = cb[slot * 256 + c];
    else if (slot < 8)  b = bb[(slot - 4) * 256 + c];
    else if (slot == 8) { if (c < 80) b = sb[c]; }
    else                { if (c < 4) b = pb[c]; else if (c == 4) b = tb[0]; }
    g_bias[slot * 256 + c] = b;
}

// winograd weight transform -> bf16 hi/lo, [slot][xn][oc][k=ic]. grid (256, 10)
__global__ __launch_bounds__(256) void uwt_k(
    const float* __restrict__ cw, const float* __restrict__ bw,
    const float* __restrict__ sw, const float* __restrict__ pw,
    const float* __restrict__ tw)
{
    int slot = blockIdx.y;
    int idx = blockIdx.x * 256 + threadIdx.x;
    int ic = idx & 255, oc = idx >> 8;
    float gg[9];
    const float* g = nullptr;
    if (slot < 4)       g = cw + ((size_t)(slot * 256 + oc) * 256 + ic) * 9;
    else if (slot < 8)  g = bw + ((size_t)((slot - 4) * 256 + oc) * 256 + ic) * 9;
    else if (slot == 8) { if (oc < 80) g = sw + ((size_t)oc * 256 + ic) * 9; }
    else                { if (oc < 4) g = pw + ((size_t)oc * 256 + ic) * 9;
                          else if (oc == 4) g = tw + (size_t)ic * 9; }
#pragma unroll
    for (int j = 0; j < 9; j++) gg[j] = g ? g[j] : 0.f;

    float G0[3], T1[3], T2[3], G2[3];
#pragma unroll
    for (int j = 0; j < 3; j++) {
        float a = gg[j], b = gg[3 + j], c = gg[6 + j];
        G0[j] = a;
        T1[j] = 0.5f * (a + b + c);
        T2[j] = 0.5f * (a - b + c);
        G2[j] = c;
    }
    float u[16];
    const float* rows[4] = {G0, T1, T2, G2};
#pragma unroll
    for (int i = 0; i < 4; i++) {
        const float* t = rows[i];
        u[i * 4 + 0] = t[0];
        u[i * 4 + 1] = 0.5f * (t[0] + t[1] + t[2]);
        u[i * 4 + 2] = 0.5f * (t[0] - t[1] + t[2]);
        u[i * 4 + 3] = t[2];
    }
#pragma unroll
    for (int x = 0; x < 16; x++) {
        float f = u[x];
        __nv_bfloat16 h = __float2bfloat16(f);
        __nv_bfloat16 lo = __float2bfloat16(f - __bfloat162float(h));
        size_t off = (((size_t)(slot * 16 + x) * 256 + oc) * 256 + ic);
        g_Uh[off] = h;
        g_Ul[off] = lo;
    }
}

// ============ winograd input transform -> bf16 hi/lo, [xn][col][k=ic] ============
__global__ __launch_bounds__(256) void itr_k(P5 X, int tower, int useaff)
{
    __shared__ float s[16][8][33];
    const int tid = threadIdx.x;
    const int lane = tid & 31, wid = tid >> 5;
    const int col = blockIdx.x * 32 + lane;
    const int icb = blockIdx.y * 8;
    const int ic = icb + wid;

    float v[16];
    {
        bool oob = (col >= COLS_T);
        int lc = oob ? 0 : col;
        int n = 0;
        if (lc >= 5350) { n = 1; lc -= 5350; }
        int l = 0;
#pragma unroll
        for (int q = 0; q < 4; q++) if (lc >= c_lt2[q]) l = q + 1;
        int tile = lc - c_lo2[l];
        int tw2 = c_tw2[l];
        int ty = tile / tw2, tx = tile - ty * tw2;
        int H = c_H[l], W = c_W[l];
        const float* x = X.p[l] + ((size_t)n * 256 + ic) * H * W;
        float sa = 1.f, sb = 0.f;
        if (useaff) {
            int as = (tower * 5 + l) * 512 + n * 256 + ic;
            sa = g_affs[as]; sb = g_affb[as];
        }
        int h0 = 2 * ty - 1, w0 = 2 * tx - 1;
        float d[4][4];
#pragma unroll
        for (int r = 0; r < 4; r++) {
            int h = h0 + r;
#pragma unroll
            for (int c = 0; c < 4; c++) {
                int w = w0 + c;
                float vv = 0.f;
                if (!oob && h >= 0 && h < H && w >= 0 && w < W) {
                    vv = x[h * W + w];
                    if (useaff) vv = fmaxf(fmaf(vv, sa, sb), 0.f);
                }
                d[r][c] = vv;
            }
        }
        float z[4][4];
#pragma unroll
        for (int j = 0; j < 4; j++) {
            z[0][j] = d[0][j] - d[2][j];
            z[1][j] = d[1][j] + d[2][j];
            z[2][j] = d[2][j] - d[1][j];
            z[3][j] = d[1][j] - d[3][j];
        }
#pragma unroll
        for (int i = 0; i < 4; i++) {
            v[i * 4 + 0] = z[i][0] - z[i][2];
            v[i * 4 + 1] = z[i][1] + z[i][2];
            v[i * 4 + 2] = z[i][2] - z[i][1];
            v[i * 4 + 3] = z[i][1] - z[i][3];
        }
    }
#pragma unroll
    for (int x = 0; x < 16; x++) s[x][wid][lane] = v[x];
    __syncthreads();

#pragma unroll
    for (int r = 0; r < 2; r++) {
        int p = tid + 256 * r;
        int xn = p >> 5, c = p & 31;
        int col2 = blockIdx.x * 32 + c;
        union { __nv_bfloat16 b[8]; uint4 q; } hh, ll;
#pragma unroll
        for (int i = 0; i < 8; i++) {
            float f = s[xn][i][c];
            __nv_bfloat16 h = __float2bfloat16(f);
            hh.b[i] = h;
            ll.b[i] = __float2bfloat16(f - __bfloat162float(h));
        }
        size_t off = ((size_t)xn * CPAD + col2) * 256 + icb;
        *(uint4*)(g_Vh + off) = hh.q;
        *(uint4*)(g_Vl + off) = ll.q;
    }
}

// ============ HMMA GEMM: M[mo][xn][col][oc] = sum over 3 bf16-split terms ============
// CTA 128col x 128oc, 8 warps (4x2); k64 chunks (12 iters); 3-stage cp.async ring.
#define MG_SMEM (3 * 32768)

__global__ __launch_bounds__(256, 2) void mmag_k(int slot, int mo)
{
    extern __shared__ char mgsm[];

    const int tid = threadIdx.x, lane = tid & 31, wid = tid >> 5;
    const int cb = blockIdx.x, ob = blockIdx.y, xn = blockIdx.z;
    const int wm = (wid & 3) * 32, wn = (wid >> 2) * 64;
    const unsigned sbu = (unsigned)__cvta_generic_to_shared(mgsm);

    const size_t aRow = ((size_t)xn * CPAD + (size_t)cb * 128);          // * 256 elems
    const size_t bRow = ((size_t)(slot * 16 + xn) * 256 + ob * 128);     // * 256 elems

    float acc[2][8][4];
#pragma unroll
    for (int mt = 0; mt < 2; mt++)
#pragma unroll
        for (int nt = 0; nt < 8; nt++)
#pragma unroll
            for (int e = 0; e < 4; e++) acc[mt][nt][e] = 0.f;

    auto stage = [&](int buf, int it) {
        const int t = it >> 2, kk = (it & 3) << 6;
        const __nv_bfloat16* A = (t < 2) ? g_Vh : g_Vl;
        const __nv_bfloat16* B = (t == 1) ? g_Ul : g_Uh;
#pragma unroll
        for (int j = 0; j < 4; j++) {
            int idx = tid + j * 256;
            int r = idx >> 3, c = idx & 7;
            unsigned d = sbu + buf * 32768 + r * 128 + ((c ^ (r & 7)) << 4);
            CP16(d, (const char*)(A + (aRow + r) * 256 + kk) + c * 16);
        }
#pragma unroll
        for (int j = 0; j < 4; j++) {
            int idx = tid + j * 256;
            int r = idx >> 3, c = idx & 7;
            unsigned d = sbu + buf * 32768 + 16384 + r * 128 + ((c ^ (r & 7)) << 4);
            CP16(d, (const char*)(B + (bRow + r) * 256 + kk) + c * 16);
        }
        CP_COMMIT();
    };

    stage(0, 0);
    stage(1, 1);

    for (int it = 0; it < 12; it++) {
        const int buf = it % 3;
        if (it < 10)      { stage((it + 2) % 3, it + 2); CP_WAIT2(); }
        else if (it == 10) CP_WAIT1();
        else               CP_WAIT0();
        __syncthreads();

        const unsigned sA = sbu + buf * 32768;
        const unsigned sB = sA + 16384;
#pragma unroll
        for (int k16 = 0; k16 < 4; k16++) {
            unsigned a[2][4];
#pragma unroll
            for (int mt = 0; mt < 2; mt++) {
                int row = wm + mt * 16 + (lane & 15);
                int lc = 2 * k16 + (lane >> 4);
                unsigned ad = sA + row * 128 + ((lc ^ (row & 7)) << 4);
                LDSM4(a[mt][0], a[mt][1], a[mt][2], a[mt][3], ad);
            }
#pragma unroll
            for (int np = 0; np < 4; np++) {
                int row = wn + np * 16 + (lane & 7) + ((lane >> 4) << 3);
                int lc = 2 * k16 + ((lane >> 3) & 1);
                unsigned bd = sB + row * 128 + ((lc ^ (row & 7)) << 4);
                unsigned b0, b1, b2, b3;
                LDSM4(b0, b1, b2, b3, bd);
#pragma unroll
                for (int mt = 0; mt < 2; mt++) {
                    MMA16816(acc[mt][2*np][0], acc[mt][2*np][1],
                             acc[mt][2*np][2], acc[mt][2*np][3],
                             a[mt][0], a[mt][1], a[mt][2], a[mt][3], b0, b1);
                    MMA16816(acc[mt][2*np+1][0], acc[mt][2*np+1][1],
                             acc[mt][2*np+1][2], acc[mt][2*np+1][3],
                             a[mt][0], a[mt][1], a[mt][2], a[mt][3], b2, b3);
                }
            }
        }
        __syncthreads();
    }

    const int q = lane >> 2, oc2 = 2 * (lane & 3);
#pragma unroll
    for (int mt = 0; mt < 2; mt++) {
#pragma unroll
        for (int rr = 0; rr < 2; rr++) {
            int col = cb * 128 + wm + mt * 16 + q + rr * 8;
            if (col >= COLS_T) continue;
            float* Mp = g_M + ((size_t)(mo * 16 + xn) * CPAD + col) * 256 + ob * 128 + wn + oc2;
#pragma unroll
            for (int nt = 0; nt < 8; nt++)
                *(float2*)(Mp + nt * 8) = make_float2(acc[mt][nt][rr * 2],
                                                      acc[mt][nt][rr * 2 + 1]);
        }
    }
}

__device__ __forceinline__ void coldec(int col, int& n, int& l, int& ty, int& tx)
{
    n = 0; int lc = col;
    if (lc >= 5350) { n = 1; lc -= 5350; }
    l = 0;
#pragma unroll
    for (int q = 0; q < 4; q++) if (lc >= c_lt2[q]) l = q + 1;
    int tile = lc - c_lo2[l];
    int tw2 = c_tw2[l];
    ty = tile / tw2; tx = tile - ty * tw2;
}

__device__ __forceinline__ void otr_core(const float* Mp, float bias,
                                         float& y00, float& y01, float& y10, float& y11)
{
    float m[16];
#pragma unroll
    for (int x = 0; x < 16; x++) m[x] = Mp[(size_t)x * CPAD * 256];
    float s0[4], s1[4];
#pragma unroll
    for (int j = 0; j < 4; j++) {
        s0[j] = m[j] + m[4 + j] + m[8 + j];
        s1[j] = m[4 + j] - m[8 + j] - m[12 + j];
    }
    y00 = s0[0] + s0[1] + s0[2] + bias;
    y01 = s0[1] - s0[2] - s0[3] + bias;
    y10 = s1[0] + s1[1] + s1[2] + bias;
    y11 = s1[1] - s1[2] - s1[3] + bias;
}

// ============ tower output transform: raw conv out (pre-GN) ============
__global__ __launch_bounds__(256) void otr_k(P5o Y, int slot)
{
    int oc = threadIdx.x;
    int col = blockIdx.x;
    int n, l, ty, tx;
    coldec(col, n, l, ty, tx);
    int H = c_H[l], W = c_W[l];

    float y00, y01, y10, y11;
    otr_core(g_M + (size_t)col * 256 + oc, g_bias[slot * 256 + oc], y00, y01, y10, y11);

    float* y = Y.p[l] + ((size_t)n * 256 + oc) * H * W;
    int h0 = 2 * ty, w0 = 2 * tx;
    y[h0 * W + w0] = y00;
    if (w0 + 1 < W) y[h0 * W + w0 + 1] = y01;
    if (h0 + 1 < H) {
        y[(h0 + 1) * W + w0] = y10;
        if (w0 + 1 < W) y[(h0 + 1) * W + w0 + 1] = y11;
    }
}

// ============ merged head output transform. grid COLS_T, 128 thr ============
// threads 96..100: box decode (M[1], slot 9) -> boxes; sigmoid(ctr) -> smem
// threads 0..79:   score (M[0], slot 8) * sigmoid(ctr) -> scores
__global__ __launch_bounds__(128) void otrH_k(float* __restrict__ out,
                                              const float* __restrict__ scales)
{
    __shared__ float sc4[4];
    int tid = threadIdx.x;
    int col = blockIdx.x;
    int n, l, ty, tx;
    coldec(col, n, l, ty, tx);
    int H = c_H[l], W = c_W[l];
    int h0 = 2 * ty, w0 = 2 * tx;

    if (tid >= 96 && tid <= 100) {
        int oc = tid - 96;
        float st = c_str[l];
        float sl = scales[l];
        float y4[4];
        otr_core(g_M + ((size_t)16 * CPAD + col) * 256 + oc,
                 g_bias[9 * 256 + oc], y4[0], y4[1], y4[2], y4[3]);
#pragma unroll
        for (int dy = 0; dy < 2; dy++)
#pragma unroll
            for (int dx = 0; dx < 2; dx++) {
                int gh = h0 + dy, gw = w0 + dx;
                if (gh >= H || gw >= W) continue;
                float v = y4[dy * 2 + dx];
                int pix = c_off[l] + gh * W + gw;
                if (oc == 4) {
                    sc4[dy * 2 + dx] = sigmoidf_(v);
                } else {
                    float rg = fmaxf(v * sl, 0.f) * st;
                    float sh = (oc & 1) ? gh * st : gw * st;
                    out[((size_t)n * TOT + pix) * 84 + 80 + oc] = (oc < 2) ? sh - rg : sh + rg;
                }
            }
    }
    __syncthreads();

    if (tid < 80) {
        int oc = tid;
        float y4[4];
        otr_core(g_M + (size_t)col * 256 + oc, g_bias[8 * 256 + oc],
                 y4[0], y4[1], y4[2], y4[3]);
        size_t base = (size_t)n * TOT;
#pragma unroll
        for (int dy = 0; dy < 2; dy++)
#pragma unroll
            for (int dx = 0; dx < 2; dx++) {
                int gh = h0 + dy, gw = w0 + dx;
                if (gh >= H || gw >= W) continue;
                int pix = c_off[l] + gh * W + gw;
                out[(base + pix) * 84 + oc] = sigmoidf_(y4[dy * 2 + dx]) * sc4[dy * 2 + dx];
            }
    }
}

// ============ GN stats ============
__global__ __launch_bounds__(256) void gnpm_k(const float* __restrict__ buf, int pp)
{
    const int tid = threadIdx.x;
    const int b = blockIdx.x >> 6;
    const int ng = blockIdx.x & 63;
    const int s = blockIdx.y;
    const int t = b / 5, l = b % 5;
    const int nn = ng >> 5, g = ng & 31;
    const int HW = c_HW[l];
    const float* p = buf + (size_t)(t * 2 + pp) * LVL_ELEMS + (size_t)512 * c_off[l]
                   + ((size_t)nn * 256 + g * 8) * HW;
    int cnt = 8 * HW;
    int chunk = (cnt + 3) >> 2;
    int beg = s * chunk, end = min(cnt, beg + chunk);

    float sm = 0.f, sq = 0.f;
    for (int i = beg + tid; i < end; i += 256) { float v = p[i]; sm += v; sq += v * v; }
    __shared__ float ss[256], sv[256];
    ss[tid] = sm; sv[tid] = sq;
    __syncthreads();
    for (int k = 128; k > 0; k >>= 1) {
        if (tid < k) { ss[tid] += ss[tid + k]; sv[tid] += sv[tid + k]; }
        __syncthreads();
    }
    if (tid == 0) {
        g_part[((b * 64 + ng) * 4 + s) * 2 + 0] = ss[0];
        g_part[((b * 64 + ng) * 4 + s) * 2 + 1] = sv[0];
    }
}

__global__ __launch_bounds__(512) void fin_k(
    const float* __restrict__ cgw, const float* __restrict__ cgb,
    const float* __restrict__ bgw, const float* __restrict__ bgb, int i)
{
    const int b = blockIdx.x;
    const int t = b / 5, l = b % 5;
    const int tid = threadIdx.x;
    const int c = tid & 255, g = c >> 3;
    const int nn = tid >> 8;
    float sm = 0.f, sq = 0.f;
#pragma unroll
    for (int s = 0; s < 4; s++) {
        sm += g_part[((b * 64 + nn * 32 + g) * 4 + s) * 2 + 0];
        sq += g_part[((b * 64 + nn * 32 + g) * 4 + s) * 2 + 1];
    }
    float inv = 1.f / (8.f * (float)c_HW[l]);
    float mean = sm * inv;
    float var = sq * inv - mean * mean;
    float rstd = rsqrtf(var + 1e-5f);
    const float* gw = t ? bgw : cgw;
    const float* gb = t ? bgb : cgb;
    float sc = gw[i * 256 + c] * rstd;
    g_affs[b * 512 + tid] = sc;
    g_affb[b * 512 + tid] = gb[i * 256 + c] - mean * sc;
}

// ============ host ============
extern "C" void kernel_launch(void* const* d_in, const int* in_sizes, int n_in,
                              void* d_out, int out_size)
{
    (void)in_sizes; (void)n_in; (void)out_size;

    const float* feats[5];
    for (int i = 0; i < 5; i++) feats[i] = (const float*)d_in[i];
    const float* cls_w  = (const float*)d_in[5];
    const float* cls_b  = (const float*)d_in[6];
    const float* cls_gw = (const float*)d_in[7];
    const float* cls_gb = (const float*)d_in[8];
    const float* box_w  = (const float*)d_in[9];
    const float* box_b  = (const float*)d_in[10];
    const float* box_gw = (const float*)d_in[11];
    const float* box_gb = (const float*)d_in[12];
    const float* score_w = (const float*)d_in[13];
    const float* score_b = (const float*)d_in[14];
    const float* pred_w  = (const float*)d_in[15];
    const float* pred_b  = (const float*)d_in[16];
    const float* ctr_w   = (const float*)d_in[17];
    const float* ctr_b   = (const float*)d_in[18];
    const float* scales  = (const float*)d_in[19];
    float* out = (float*)d_out;

    float* bufp;
    cudaGetSymbolAddress((void**)&bufp, g_buf);
    auto lvl = [&](int t, int pp, int l) {
        return bufp + (size_t)(t * 2 + pp) * LVL_ELEMS + (size_t)512 * OFFS[l];
    };
    auto mkP5o = [&](int t, int pp) {
        P5o y; for (int l = 0; l < 5; l++) y.p[l] = lvl(t, pp, l); return y;
    };
    auto mkP5 = [&](int t, int pp) {
        P5 y; for (int l = 0; l < 5; l++) y.p[l] = lvl(t, pp, l); return y;
    };

    cudaFuncSetAttribute(mmag_k, cudaFuncAttributeMaxDynamicSharedMemorySize, MG_SMEM);

    dim3 blk(256);
    dim3 mgrid(84, 2, 16);
    dim3 hgrid(84, 1, 16);

    // one-time weight prep
    bias_k<<<10, blk>>>(cls_b, box_b, score_b, pred_b, ctr_b);
    uwt_k<<<dim3(256, 10), blk>>>(cls_w, box_w, score_w, pred_w, ctr_w);

    // depth 0: shared input transform (feats, no affine)
    {
        P5 F; for (int l = 0; l < 5; l++) F.p[l] = feats[l];
        itr_k<<<dim3(335, 32), blk>>>(F, 0, 0);
        mmag_k<<<mgrid, blk, MG_SMEM>>>(0, 0);
        otr_k<<<COLS_T, blk>>>(mkP5o(0, 0), 0);
        mmag_k<<<mgrid, blk, MG_SMEM>>>(4, 0);
        otr_k<<<COLS_T, blk>>>(mkP5o(1, 0), 4);
        gnpm_k<<<dim3(640, 4), blk>>>(bufp, 0);
        fin_k<<<10, 512>>>(cls_gw, cls_gb, box_gw, box_gb, 0);
    }
    // depths 1..3
    for (int i = 1; i < 4; i++) {
        for (int t = 0; t < 2; t++) {
            itr_k<<<dim3(335, 32), blk>>>(mkP5(t, (i - 1) & 1), t, 1);
            mmag_k<<<mgrid, blk, MG_SMEM>>>(t * 4 + i, 0);
            otr_k<<<COLS_T, blk>>>(mkP5o(t, i & 1), t * 4 + i);
        }
        gnpm_k<<<dim3(640, 4), blk>>>(bufp, i & 1);
        fin_k<<<10, 512>>>(cls_gw, cls_gb, box_gw, box_gb, i);
    }

    // heads via winograd (inputs: depth-3 outputs, pp=1; affines i=3)
    itr_k<<<dim3(335, 32), blk>>>(mkP5(0, 1), 0, 1);   // cls tower final
    mmag_k<<<hgrid, blk, MG_SMEM>>>(8, 0);             // score -> M[0]
    itr_k<<<dim3(335, 32), blk>>>(mkP5(1, 1), 1, 1);   // box tower final
    mmag_k<<<hgrid, blk, MG_SMEM>>>(9, 1);             // pred+ctr -> M[1]
    otrH_k<<<COLS_T, 128>>>(out, scales);
}